// round 13
// baseline (speedup 1.0000x reference)
#include <cuda_runtime.h>
#include <cuda_fp16.h>

#define NB 16
#define HH 512
#define WW 512
#define HQ 256
#define WQ 256
#define RAD 7

// Scratch (device globals; allocation in kernel_launch is forbidden)
__device__ __half g_yh[NB * HH * WW];        // horizontally filtered Y diff (fp16)
__device__ __half g_ch[2 * NB * HQ * WQ];    // horizontally filtered chroma (fp16)
__device__ double g_acc[2];                  // [0]=Y sumsq, [1]=U+V sumsq
__device__ unsigned int g_done;              // completion counter (self-resetting)

// ---------------------------------------------------------------------------
// k_diff_h: YUV420 diff channels + horizontal 15-tap box filter, fused.
// One warp = one Y row-pair = one chroma row. grid 512, block 256 (8 warps).
// Outputs stored as fp16. (Unchanged — at its DRAM floor.)
// ---------------------------------------------------------------------------
__global__ void __launch_bounds__(256)
k_diff_h(const float* __restrict__ in, const float* __restrict__ tg) {
    __shared__ float sP[8][WW + 16];    // per-warp prefix buffer
    __shared__ float sC[8][2 * WQ];     // per-warp raw chroma rows (U|V)

    const unsigned FULL = 0xFFFFFFFFu;
    int warp = threadIdx.x >> 5;
    int lane = threadIdx.x & 31;

    if (blockIdx.x == 0 && threadIdx.x < 2) g_acc[threadIdx.x] = 0.0;

    int gw = blockIdx.x * 8 + warp;     // 0..4095 row-pairs
    int n  = gw >> 8;                   // image
    int hq = gw & 255;                  // chroma row / y row-pair

    const long plane = (long)HH * WW;
    const long p4 = plane >> 2, w4 = WW >> 2;
    long base4 = ((long)n * 3 * plane + (long)(2 * hq) * WW) >> 2;

    const float4* i4 = (const float4*)in;
    const float4* t4 = (const float4*)tg;

    float* U = sC[warp];
    float* V = sC[warp] + WQ;
    float* P = sP[warp];

    float4 yd0[4], yd1[4];

    #pragma unroll
    for (int c = 0; c < 4; ++c) {
        long o = base4 + c * 32 + lane;
        float4 a, b, dr0, dg0, db0, dr1, dg1, db1;
        a = i4[o];            b = t4[o];
        dr0 = make_float4(a.x-b.x, a.y-b.y, a.z-b.z, a.w-b.w);
        a = i4[o + p4];       b = t4[o + p4];
        dg0 = make_float4(a.x-b.x, a.y-b.y, a.z-b.z, a.w-b.w);
        a = i4[o + 2*p4];     b = t4[o + 2*p4];
        db0 = make_float4(a.x-b.x, a.y-b.y, a.z-b.z, a.w-b.w);
        a = i4[o + w4];       b = t4[o + w4];
        dr1 = make_float4(a.x-b.x, a.y-b.y, a.z-b.z, a.w-b.w);
        a = i4[o + w4 + p4];  b = t4[o + w4 + p4];
        dg1 = make_float4(a.x-b.x, a.y-b.y, a.z-b.z, a.w-b.w);
        a = i4[o + w4 + 2*p4];b = t4[o + w4 + 2*p4];
        db1 = make_float4(a.x-b.x, a.y-b.y, a.z-b.z, a.w-b.w);

        yd0[c] = make_float4(0.299f*dr0.x + 0.587f*dg0.x + 0.114f*db0.x,
                             0.299f*dr0.y + 0.587f*dg0.y + 0.114f*db0.y,
                             0.299f*dr0.z + 0.587f*dg0.z + 0.114f*db0.z,
                             0.299f*dr0.w + 0.587f*dg0.w + 0.114f*db0.w);
        yd1[c] = make_float4(0.299f*dr1.x + 0.587f*dg1.x + 0.114f*db1.x,
                             0.299f*dr1.y + 0.587f*dg1.y + 0.114f*db1.y,
                             0.299f*dr1.z + 0.587f*dg1.z + 0.114f*db1.z,
                             0.299f*dr1.w + 0.587f*dg1.w + 0.114f*db1.w);

        float drA = dr0.x + dr0.y + dr1.x + dr1.y;
        float dgA = dg0.x + dg0.y + dg1.x + dg1.y;
        float dbA = db0.x + db0.y + db1.x + db1.y;
        float drB = dr0.z + dr0.w + dr1.z + dr1.w;
        float dgB = dg0.z + dg0.w + dg1.z + dg1.w;
        float dbB = db0.z + db0.w + db1.z + db1.w;

        *(float2*)(U + c*64 + 2*lane) =
            make_float2(0.25f * (-0.169f*drA - 0.331f*dgA + 0.5f*dbA),
                        0.25f * (-0.169f*drB - 0.331f*dgB + 0.5f*dbB));
        *(float2*)(V + c*64 + 2*lane) =
            make_float2(0.25f * ( 0.5f*drA - 0.46f*dgA - 0.04f*dbA),
                        0.25f * ( 0.5f*drB - 0.46f*dgB - 0.04f*dbB));
    }
    __syncwarp();

    // ---- horizontal box filter of one row via prefix sum, emit fp16 ----
    // Y rows from registers
    #pragma unroll
    for (int r = 0; r < 2; ++r) {
        float4* Y = r ? yd1 : yd0;
        if (lane < 8) P[lane] = 0.f;
        float carry = 0.f;
        #pragma unroll
        for (int c = 0; c < 4; ++c) {
            float4 v = Y[c];
            float p1 = v.x + v.y, p2 = p1 + v.z, p3 = p2 + v.w;
            float tt = p3;
            #pragma unroll
            for (int off = 1; off < 32; off <<= 1) {
                float o = __shfl_up_sync(FULL, tt, off);
                if (lane >= off) tt += o;
            }
            float bb = tt - p3 + carry;
            ((float4*)(P + 8))[c * 32 + lane] =
                make_float4(bb + v.x, bb + p1, bb + p2, bb + p3);
            carry += __shfl_sync(FULL, tt, 31);
        }
        __syncwarp();
        if (lane < 7) P[8 + WW + lane] = carry;
        __syncwarp();
        __half* dst = g_yh + (long)n * plane + (long)(2*hq + r) * WW;
        #pragma unroll
        for (int c = 0; c < 4; ++c) {
            int x = c * 128 + 4 * lane;
            float4 b = ((const float4*)P)[x >> 2];
            __half2 h01 = __floats2half2_rn(P[x + 15] - b.x, P[x + 16] - b.y);
            __half2 h23 = __floats2half2_rn(P[x + 17] - b.z, P[x + 18] - b.w);
            uint2 st;
            st.x = *(unsigned*)&h01;
            st.y = *(unsigned*)&h23;
            *(uint2*)(dst + x) = st;
        }
        __syncwarp();
    }

    // Chroma rows from smem staging
    #pragma unroll
    for (int r = 0; r < 2; ++r) {
        const float* R = r ? V : U;
        if (lane < 8) P[lane] = 0.f;
        float carry = 0.f;
        #pragma unroll
        for (int c = 0; c < 2; ++c) {
            float4 v = ((const float4*)R)[c * 32 + lane];
            float p1 = v.x + v.y, p2 = p1 + v.z, p3 = p2 + v.w;
            float tt = p3;
            #pragma unroll
            for (int off = 1; off < 32; off <<= 1) {
                float o = __shfl_up_sync(FULL, tt, off);
                if (lane >= off) tt += o;
            }
            float bb = tt - p3 + carry;
            ((float4*)(P + 8))[c * 32 + lane] =
                make_float4(bb + v.x, bb + p1, bb + p2, bb + p3);
            carry += __shfl_sync(FULL, tt, 31);
        }
        __syncwarp();
        if (lane < 7) P[8 + WQ + lane] = carry;
        __syncwarp();
        __half* dst = g_ch + ((long)(r * NB + n) * HQ + hq) * WQ;
        #pragma unroll
        for (int c = 0; c < 2; ++c) {
            int x = c * 128 + 4 * lane;
            float4 b = ((const float4*)P)[x >> 2];
            __half2 h01 = __floats2half2_rn(P[x + 15] - b.x, P[x + 16] - b.y);
            __half2 h23 = __floats2half2_rn(P[x + 17] - b.z, P[x + 18] - b.w);
            uint2 st;
            st.x = *(unsigned*)&h01;
            st.y = *(unsigned*)&h23;
            *(uint2*)(dst + x) = st;
        }
        __syncwarp();
    }
}

// ---------------------------------------------------------------------------
// k_v: vertical 15-tap box (zero-pad SAME). MLP batch (22 up-front loads)
// + RGRP=8 for 2x grid: 196,608 tasks = 768 blocks x 256 threads,
// launch_bounds(256,4) pins 4 blocks/SM residency.
// Tasks 0..131071: Y (4 cols x 8 rows). 131072..196607: chroma.
// ---------------------------------------------------------------------------
#define NBLK_V 768
#define RGRP 8
#define WROWS (RGRP + 2 * RAD)   // 22

__global__ void __launch_bounds__(256, 4)
k_v(float* __restrict__ out) {
    __shared__ double red[8];
    const unsigned FULL = 0xFFFFFFFFu;

    int t = blockIdx.x * 256 + threadIdx.x;
    bool isY = t < 131072;

    const __half* src; int H, y0; long stride;
    if (isY) {
        int colg = t & 127, rowg = (t >> 7) & 63, n = t >> 13;
        H = HH; stride = WW; y0 = rowg * RGRP;
        src = g_yh + (long)n * HH * WW + 4 * colg;
    } else {
        int t2 = t - 131072;
        int colg = t2 & 63, rowg = (t2 >> 6) & 31, pl = t2 >> 11;  // 0..31
        H = HQ; stride = WQ; y0 = rowg * RGRP;
        src = g_ch + (long)pl * HQ * WQ + 4 * colg;
    }

    // ---- batch-issue all 22 independent loads (max MLP) ----
    uint2 r[WROWS];
    #pragma unroll
    for (int j = 0; j < WROWS; ++j) {
        int yy = y0 + j - RAD;
        if (yy >= 0 && yy < H)
            r[j] = *(const uint2*)(src + (long)yy * stride);
        else
            r[j] = make_uint2(0u, 0u);
    }

    // ---- sliding window entirely in registers ----
    float4 sum = make_float4(0.f, 0.f, 0.f, 0.f);
    #pragma unroll
    for (int j = 0; j < 15; ++j) {
        float2 lo = __half22float2(*(__half2*)&r[j].x);
        float2 hi = __half22float2(*(__half2*)&r[j].y);
        sum.x += lo.x; sum.y += lo.y; sum.z += hi.x; sum.w += hi.y;
    }
    float racc = 0.f;
    #pragma unroll
    for (int i = 0; i < RGRP; ++i) {
        racc += sum.x*sum.x + sum.y*sum.y + sum.z*sum.z + sum.w*sum.w;
        if (i < RGRP - 1) {
            float2 alo = __half22float2(*(__half2*)&r[i + 15].x);
            float2 ahi = __half22float2(*(__half2*)&r[i + 15].y);
            float2 rlo = __half22float2(*(__half2*)&r[i].x);
            float2 rhi = __half22float2(*(__half2*)&r[i].y);
            sum.x += alo.x - rlo.x; sum.y += alo.y - rlo.y;
            sum.z += ahi.x - rhi.x; sum.w += ahi.y - rhi.y;
        }
    }
    double dacc = (double)racc;

    #pragma unroll
    for (int off = 16; off > 0; off >>= 1)
        dacc += __shfl_down_sync(FULL, dacc, off);
    int warp = threadIdx.x >> 5, lane = threadIdx.x & 31;
    if (lane == 0) red[warp] = dacc;
    __syncthreads();
    if (threadIdx.x == 0) {
        double s = 0.0;
        #pragma unroll
        for (int w = 0; w < 8; ++w) s += red[w];
        atomicAdd(&g_acc[isY ? 0 : 1], s);
        __threadfence();
        unsigned int prev = atomicAdd(&g_done, 1u);
        if (prev == NBLK_V - 1) {
            volatile double* acc = g_acc;
            double y = acc[0] / (double)((long)NB * HH * WW);
            double c = acc[1] / (double)((long)NB * HQ * WQ);
            out[0] = (float)(y + c);
            g_done = 0u;
        }
    }
}

extern "C" void kernel_launch(void* const* d_in, const int* in_sizes, int n_in,
                              void* d_out, int out_size) {
    const float* in = (const float*)d_in[0];
    const float* tg = (const float*)d_in[1];
    float* out = (float*)d_out;
    (void)in_sizes; (void)n_in; (void)out_size;

    k_diff_h<<<512, 256>>>(in, tg);
    k_v<<<NBLK_V, 256>>>(out);
}

// round 14
// speedup vs baseline: 1.0626x; 1.0626x over previous
#include <cuda_runtime.h>
#include <cuda_fp16.h>

#define NB 16
#define HH 512
#define WW 512
#define HQ 256
#define WQ 256
#define RAD 7

// Scratch (device globals; allocation in kernel_launch is forbidden)
__device__ __half g_yh[NB * HH * WW];        // horizontally filtered Y diff (fp16)
__device__ __half g_ch[2 * NB * HQ * WQ];    // horizontally filtered chroma (fp16)
__device__ double g_acc[2];                  // [0]=Y sumsq, [1]=U+V sumsq
__device__ unsigned int g_done;              // completion counter (self-resetting)

// ---------------------------------------------------------------------------
// k_diff_h: YUV420 diff channels + horizontal 15-tap box filter, fused.
// One warp = one Y row-pair = one chroma row. grid 512, block 256 (8 warps).
// Input reads use __ldcs (evict-first): the 100MB of inputs is single-use, and
// caching it evicts the g_yh/g_ch intermediates that k_v needs L2-resident.
// ---------------------------------------------------------------------------
__global__ void __launch_bounds__(256)
k_diff_h(const float* __restrict__ in, const float* __restrict__ tg) {
    __shared__ float sP[8][WW + 16];    // per-warp prefix buffer
    __shared__ float sC[8][2 * WQ];     // per-warp raw chroma rows (U|V)

    const unsigned FULL = 0xFFFFFFFFu;
    int warp = threadIdx.x >> 5;
    int lane = threadIdx.x & 31;

    if (blockIdx.x == 0 && threadIdx.x < 2) g_acc[threadIdx.x] = 0.0;

    int gw = blockIdx.x * 8 + warp;     // 0..4095 row-pairs
    int n  = gw >> 8;                   // image
    int hq = gw & 255;                  // chroma row / y row-pair

    const long plane = (long)HH * WW;
    const long p4 = plane >> 2, w4 = WW >> 2;
    long base4 = ((long)n * 3 * plane + (long)(2 * hq) * WW) >> 2;

    const float4* i4 = (const float4*)in;
    const float4* t4 = (const float4*)tg;

    float* U = sC[warp];
    float* V = sC[warp] + WQ;
    float* P = sP[warp];

    float4 yd0[4], yd1[4];

    #pragma unroll
    for (int c = 0; c < 4; ++c) {
        long o = base4 + c * 32 + lane;
        float4 a, b, dr0, dg0, db0, dr1, dg1, db1;
        a = __ldcs(i4 + o);             b = __ldcs(t4 + o);
        dr0 = make_float4(a.x-b.x, a.y-b.y, a.z-b.z, a.w-b.w);
        a = __ldcs(i4 + o + p4);        b = __ldcs(t4 + o + p4);
        dg0 = make_float4(a.x-b.x, a.y-b.y, a.z-b.z, a.w-b.w);
        a = __ldcs(i4 + o + 2*p4);      b = __ldcs(t4 + o + 2*p4);
        db0 = make_float4(a.x-b.x, a.y-b.y, a.z-b.z, a.w-b.w);
        a = __ldcs(i4 + o + w4);        b = __ldcs(t4 + o + w4);
        dr1 = make_float4(a.x-b.x, a.y-b.y, a.z-b.z, a.w-b.w);
        a = __ldcs(i4 + o + w4 + p4);   b = __ldcs(t4 + o + w4 + p4);
        dg1 = make_float4(a.x-b.x, a.y-b.y, a.z-b.z, a.w-b.w);
        a = __ldcs(i4 + o + w4 + 2*p4); b = __ldcs(t4 + o + w4 + 2*p4);
        db1 = make_float4(a.x-b.x, a.y-b.y, a.z-b.z, a.w-b.w);

        yd0[c] = make_float4(0.299f*dr0.x + 0.587f*dg0.x + 0.114f*db0.x,
                             0.299f*dr0.y + 0.587f*dg0.y + 0.114f*db0.y,
                             0.299f*dr0.z + 0.587f*dg0.z + 0.114f*db0.z,
                             0.299f*dr0.w + 0.587f*dg0.w + 0.114f*db0.w);
        yd1[c] = make_float4(0.299f*dr1.x + 0.587f*dg1.x + 0.114f*db1.x,
                             0.299f*dr1.y + 0.587f*dg1.y + 0.114f*db1.y,
                             0.299f*dr1.z + 0.587f*dg1.z + 0.114f*db1.z,
                             0.299f*dr1.w + 0.587f*dg1.w + 0.114f*db1.w);

        float drA = dr0.x + dr0.y + dr1.x + dr1.y;
        float dgA = dg0.x + dg0.y + dg1.x + dg1.y;
        float dbA = db0.x + db0.y + db1.x + db1.y;
        float drB = dr0.z + dr0.w + dr1.z + dr1.w;
        float dgB = dg0.z + dg0.w + dg1.z + dg1.w;
        float dbB = db0.z + db0.w + db1.z + db1.w;

        *(float2*)(U + c*64 + 2*lane) =
            make_float2(0.25f * (-0.169f*drA - 0.331f*dgA + 0.5f*dbA),
                        0.25f * (-0.169f*drB - 0.331f*dgB + 0.5f*dbB));
        *(float2*)(V + c*64 + 2*lane) =
            make_float2(0.25f * ( 0.5f*drA - 0.46f*dgA - 0.04f*dbA),
                        0.25f * ( 0.5f*drB - 0.46f*dgB - 0.04f*dbB));
    }
    __syncwarp();

    // ---- horizontal box filter of one row via prefix sum, emit fp16 ----
    // Y rows from registers
    #pragma unroll
    for (int r = 0; r < 2; ++r) {
        float4* Y = r ? yd1 : yd0;
        if (lane < 8) P[lane] = 0.f;
        float carry = 0.f;
        #pragma unroll
        for (int c = 0; c < 4; ++c) {
            float4 v = Y[c];
            float p1 = v.x + v.y, p2 = p1 + v.z, p3 = p2 + v.w;
            float tt = p3;
            #pragma unroll
            for (int off = 1; off < 32; off <<= 1) {
                float o = __shfl_up_sync(FULL, tt, off);
                if (lane >= off) tt += o;
            }
            float bb = tt - p3 + carry;
            ((float4*)(P + 8))[c * 32 + lane] =
                make_float4(bb + v.x, bb + p1, bb + p2, bb + p3);
            carry += __shfl_sync(FULL, tt, 31);
        }
        __syncwarp();
        if (lane < 7) P[8 + WW + lane] = carry;
        __syncwarp();
        __half* dst = g_yh + (long)n * plane + (long)(2*hq + r) * WW;
        #pragma unroll
        for (int c = 0; c < 4; ++c) {
            int x = c * 128 + 4 * lane;
            float4 b = ((const float4*)P)[x >> 2];
            __half2 h01 = __floats2half2_rn(P[x + 15] - b.x, P[x + 16] - b.y);
            __half2 h23 = __floats2half2_rn(P[x + 17] - b.z, P[x + 18] - b.w);
            uint2 st;
            st.x = *(unsigned*)&h01;
            st.y = *(unsigned*)&h23;
            *(uint2*)(dst + x) = st;
        }
        __syncwarp();
    }

    // Chroma rows from smem staging
    #pragma unroll
    for (int r = 0; r < 2; ++r) {
        const float* R = r ? V : U;
        if (lane < 8) P[lane] = 0.f;
        float carry = 0.f;
        #pragma unroll
        for (int c = 0; c < 2; ++c) {
            float4 v = ((const float4*)R)[c * 32 + lane];
            float p1 = v.x + v.y, p2 = p1 + v.z, p3 = p2 + v.w;
            float tt = p3;
            #pragma unroll
            for (int off = 1; off < 32; off <<= 1) {
                float o = __shfl_up_sync(FULL, tt, off);
                if (lane >= off) tt += o;
            }
            float bb = tt - p3 + carry;
            ((float4*)(P + 8))[c * 32 + lane] =
                make_float4(bb + v.x, bb + p1, bb + p2, bb + p3);
            carry += __shfl_sync(FULL, tt, 31);
        }
        __syncwarp();
        if (lane < 7) P[8 + WQ + lane] = carry;
        __syncwarp();
        __half* dst = g_ch + ((long)(r * NB + n) * HQ + hq) * WQ;
        #pragma unroll
        for (int c = 0; c < 2; ++c) {
            int x = c * 128 + 4 * lane;
            float4 b = ((const float4*)P)[x >> 2];
            __half2 h01 = __floats2half2_rn(P[x + 15] - b.x, P[x + 16] - b.y);
            __half2 h23 = __floats2half2_rn(P[x + 17] - b.z, P[x + 18] - b.w);
            uint2 st;
            st.x = *(unsigned*)&h01;
            st.y = *(unsigned*)&h23;
            *(uint2*)(dst + x) = st;
        }
        __syncwarp();
    }
}

// ---------------------------------------------------------------------------
// k_v: vertical 15-tap box (zero-pad SAME), MLP-maximized (R12 best geometry):
// 30 up-front uint2 loads, RGRP=16, 4 fp16 cols/thread, 384 blocks.
// Blocks 0..255: Y. Blocks 256..383: chroma. Fused reduce + finalize.
// ---------------------------------------------------------------------------
#define NBLK_V 384
#define RGRP 16
#define WROWS (RGRP + 2 * RAD)   // 30

__global__ void __launch_bounds__(256)
k_v(float* __restrict__ out) {
    __shared__ double red[8];
    const unsigned FULL = 0xFFFFFFFFu;

    int t = blockIdx.x * 256 + threadIdx.x;
    bool isY = t < 65536;

    const __half* src; int H, y0; long stride;
    if (isY) {
        int colg = t & 127, rowg = (t >> 7) & 31, n = t >> 12;
        H = HH; stride = WW; y0 = rowg * RGRP;
        src = g_yh + (long)n * HH * WW + 4 * colg;
    } else {
        int t2 = t - 65536;
        int colg = t2 & 63, rowg = (t2 >> 6) & 15, pl = t2 >> 10;  // 0..31
        H = HQ; stride = WQ; y0 = rowg * RGRP;
        src = g_ch + (long)pl * HQ * WQ + 4 * colg;
    }

    // ---- batch-issue all 30 independent loads (max MLP) ----
    uint2 r[WROWS];
    #pragma unroll
    for (int j = 0; j < WROWS; ++j) {
        int yy = y0 + j - RAD;
        if (yy >= 0 && yy < H)
            r[j] = *(const uint2*)(src + (long)yy * stride);
        else
            r[j] = make_uint2(0u, 0u);
    }

    // ---- sliding window entirely in registers ----
    float4 sum = make_float4(0.f, 0.f, 0.f, 0.f);
    #pragma unroll
    for (int j = 0; j < 15; ++j) {
        float2 lo = __half22float2(*(__half2*)&r[j].x);
        float2 hi = __half22float2(*(__half2*)&r[j].y);
        sum.x += lo.x; sum.y += lo.y; sum.z += hi.x; sum.w += hi.y;
    }
    float racc = 0.f;
    #pragma unroll
    for (int i = 0; i < RGRP; ++i) {
        racc += sum.x*sum.x + sum.y*sum.y + sum.z*sum.z + sum.w*sum.w;
        if (i < RGRP - 1) {
            float2 alo = __half22float2(*(__half2*)&r[i + 15].x);
            float2 ahi = __half22float2(*(__half2*)&r[i + 15].y);
            float2 rlo = __half22float2(*(__half2*)&r[i].x);
            float2 rhi = __half22float2(*(__half2*)&r[i].y);
            sum.x += alo.x - rlo.x; sum.y += alo.y - rlo.y;
            sum.z += ahi.x - rhi.x; sum.w += ahi.y - rhi.y;
        }
    }
    double dacc = (double)racc;

    #pragma unroll
    for (int off = 16; off > 0; off >>= 1)
        dacc += __shfl_down_sync(FULL, dacc, off);
    int warp = threadIdx.x >> 5, lane = threadIdx.x & 31;
    if (lane == 0) red[warp] = dacc;
    __syncthreads();
    if (threadIdx.x == 0) {
        double s = 0.0;
        #pragma unroll
        for (int w = 0; w < 8; ++w) s += red[w];
        atomicAdd(&g_acc[isY ? 0 : 1], s);
        __threadfence();
        unsigned int prev = atomicAdd(&g_done, 1u);
        if (prev == NBLK_V - 1) {
            volatile double* acc = g_acc;
            double y = acc[0] / (double)((long)NB * HH * WW);
            double c = acc[1] / (double)((long)NB * HQ * WQ);
            out[0] = (float)(y + c);
            g_done = 0u;
        }
    }
}

extern "C" void kernel_launch(void* const* d_in, const int* in_sizes, int n_in,
                              void* d_out, int out_size) {
    const float* in = (const float*)d_in[0];
    const float* tg = (const float*)d_in[1];
    float* out = (float*)d_out;
    (void)in_sizes; (void)n_in; (void)out_size;

    k_diff_h<<<512, 256>>>(in, tg);
    k_v<<<NBLK_V, 256>>>(out);
}